// round 16
// baseline (speedup 1.0000x reference)
#include <cuda_runtime.h>
#include <cuda_bf16.h>
#include <stdint.h>

// Problem: B=1024 samples, V=2, M=256 latent, C=256 categories.
// out[b] = log( S[x0[b], x1[b]] ),  S[c0,c1] = sum_q W0[q,c0] * (w_k(q) * W1[q,c1])
// q = 65536 km-pairs. Computed as split-K bf16 GEMM via mma.sync (sm_80 ISA —
// compiles at plain compute_103, unlike tcgen05 which needs the 'a' target).

#define B_SZ    1024
#define C_SZ    256
#define W1_OFF  16777216LL        // M*M*C floats = offset of W[1]
#define NCTA    2048              // 4 quadrants x 512 K-chunks
#define KCHUNK  128               // q per CTA (128 | 256 -> w_k CTA-constant)
#define THREADS 256

// SMEM: A tile 128 q-rows x 128 bf16 (256B + 16B pad = 272B pitch), B same.
// 272B pitch => row-to-row bank shift of 4 words: conflict-free STS.64 fills
// and conflict-free ldmatrix (8 row-addresses cover all 32 banks exactly once).
#define APITCH  272
#define SM_B_OFF 34816            // 128 * 272
#define SMEM_TOTAL 69632          // two tiles; epilogue stage (67584B) aliases
#define STAGE_PITCH 132           // 128 x 132 fp32 stage (pad kills conflicts)

__device__ float g_acc[B_SZ];     // indexed by ORIGINAL b; k2 reads then re-zeros

__device__ __forceinline__ unsigned smem_u32(const void* p) {
    return (unsigned)__cvta_generic_to_shared(p);
}
// pack two fp32 -> bf16x2, f_lo in low half (first source of cvt = HIGH half)
__device__ __forceinline__ uint32_t pack_bf16x2(float f_lo, float f_hi) {
    uint32_t r;
    asm("cvt.rn.bf16x2.f32 %0, %1, %2;" : "=r"(r) : "f"(f_hi), "f"(f_lo));
    return r;
}

// ---------------------------------------------------------------------------
// GEMM kernel. bid = quadrant(2b) + chunk<<2.
//   Tile fill: 256 threads LDG.128 fp32 (coalesced along c), convert to bf16
//   (B scaled by the CTA-constant w_k), STS.64 into [q][c] smem tiles.
//   Mainloop: 8 k-steps; A/B fragments via ldmatrix.x4.trans (smem is K-major
//   = transposed for row.col mma, so .trans gives exactly the mma layouts):
//     A lanes: krow = k0+(l&7)+((l>>4)<<3), mcol = m0+(l&8)
//     B lanes: krow = k0+(l&7)+(l&8),       ncol = n0+((l>>4)<<3)
//   8 warps = 4(m) x 2(n): warp tile 32x64, 64 fp32 accums/thread.
//   Epilogue: accums -> fp32 smem stage (aliases tiles after a barrier), each
//   thread checks its 4 samples and atomicAdds hits into g_acc[b].
// ---------------------------------------------------------------------------
__global__ void __launch_bounds__(THREADS, 2)
k_gemm(const int2* __restrict__ x, const float* __restrict__ W,
       const float* __restrict__ w_sum) {
    extern __shared__ char smem[];
    const int t = threadIdx.x, wid = t >> 5, l = t & 31;
    const int c0b = (blockIdx.x & 1) << 7;
    const int c1b = ((blockIdx.x >> 1) & 1) << 7;
    const int q0g = (int)(blockIdx.x >> 2) * KCHUNK;
    const float wk = __ldg(w_sum + (q0g >> 8));      // k constant per CTA

    const uint32_t smA = smem_u32(smem);
    const uint32_t smB = smA + SM_B_OFF;

    // ---- fill both tiles: warp w handles q-rows w, w+8, ..., w+120 ----
#pragma unroll
    for (int j = 0; j < 16; j++) {
        const int q = wid + 8 * j;
        const long long qq = (long long)(q0g + q) * C_SZ;
        const float4 fa = *(const float4*)(W + qq + c0b + l * 4);
        uint2 ua;
        ua.x = pack_bf16x2(fa.x, fa.y);
        ua.y = pack_bf16x2(fa.z, fa.w);
        *(uint2*)(smem + q * APITCH + l * 8) = ua;
        const float4 fb = *(const float4*)(W + W1_OFF + qq + c1b + l * 4);
        uint2 ub;
        ub.x = pack_bf16x2(fb.x * wk, fb.y * wk);
        ub.y = pack_bf16x2(fb.z * wk, fb.w * wk);
        *(uint2*)(smem + SM_B_OFF + q * APITCH + l * 8) = ub;
    }
    __syncthreads();

    // ---- mma mainloop ----
    const int wm = wid & 3, wn = wid >> 2;
    float d[2][8][4] = {};

#pragma unroll
    for (int ks = 0; ks < 8; ks++) {
        const int k0 = ks * 16;
        uint32_t a[2][4];
#pragma unroll
        for (int im = 0; im < 2; im++) {
            const uint32_t krow = (uint32_t)(k0 + (l & 7) + ((l >> 4) << 3));
            const uint32_t mcol = (uint32_t)(wm * 32 + im * 16 + (l & 8));
            const uint32_t ad = smA + krow * APITCH + mcol * 2;
            asm volatile(
                "ldmatrix.sync.aligned.m8n8.x4.trans.shared.b16 {%0,%1,%2,%3}, [%4];"
                : "=r"(a[im][0]), "=r"(a[im][1]), "=r"(a[im][2]), "=r"(a[im][3])
                : "r"(ad));
        }
#pragma unroll
        for (int inb = 0; inb < 4; inb++) {
            const uint32_t krow = (uint32_t)(k0 + (l & 7) + (l & 8));
            const uint32_t ncol = (uint32_t)(wn * 64 + inb * 16 + ((l >> 4) << 3));
            const uint32_t bd = smB + krow * APITCH + ncol * 2;
            uint32_t b0, b1, b2, b3;
            asm volatile(
                "ldmatrix.sync.aligned.m8n8.x4.trans.shared.b16 {%0,%1,%2,%3}, [%4];"
                : "=r"(b0), "=r"(b1), "=r"(b2), "=r"(b3) : "r"(bd));
#pragma unroll
            for (int im = 0; im < 2; im++) {
                asm volatile(
                    "mma.sync.aligned.m16n8k16.row.col.f32.bf16.bf16.f32 "
                    "{%0,%1,%2,%3}, {%4,%5,%6,%7}, {%8,%9}, {%0,%1,%2,%3};"
                    : "+f"(d[im][2*inb][0]), "+f"(d[im][2*inb][1]),
                      "+f"(d[im][2*inb][2]), "+f"(d[im][2*inb][3])
                    : "r"(a[im][0]), "r"(a[im][1]), "r"(a[im][2]), "r"(a[im][3]),
                      "r"(b0), "r"(b1));
                asm volatile(
                    "mma.sync.aligned.m16n8k16.row.col.f32.bf16.bf16.f32 "
                    "{%0,%1,%2,%3}, {%4,%5,%6,%7}, {%8,%9}, {%0,%1,%2,%3};"
                    : "+f"(d[im][2*inb+1][0]), "+f"(d[im][2*inb+1][1]),
                      "+f"(d[im][2*inb+1][2]), "+f"(d[im][2*inb+1][3])
                    : "r"(a[im][0]), "r"(a[im][1]), "r"(a[im][2]), "r"(a[im][3]),
                      "r"(b2), "r"(b3));
            }
        }
    }
    __syncthreads();              // all warps done reading tiles -> stage aliases

    // ---- epilogue: stage accums, gather sampled entries ----
    float* stage = (float*)smem;
    const int gr = l >> 2, gc = 2 * (l & 3);
#pragma unroll
    for (int im = 0; im < 2; im++)
#pragma unroll
        for (int jn = 0; jn < 8; jn++) {
            const int m = wm * 32 + im * 16 + gr;
            const int n = wn * 64 + jn * 8 + gc;
            // D frag: {d0,d1}=(row, col..col+1), {d2,d3}=(row+8, col..col+1)
            *(float2*)&stage[m * STAGE_PITCH + n] =
                make_float2(d[im][jn][0], d[im][jn][1]);
            *(float2*)&stage[(m + 8) * STAGE_PITCH + n] =
                make_float2(d[im][jn][2], d[im][jn][3]);
        }
    __syncthreads();

#pragma unroll
    for (int j = 0; j < 4; j++) {
        const int s = t + 256 * j;
        const int2 v = x[s];                       // (x0, x1)
        const int r = v.x - c0b, c = v.y - c1b;
        if ((unsigned)r < 128u && (unsigned)c < 128u)
            atomicAdd(&g_acc[s], stage[r * STAGE_PITCH + c]);
    }
}

// ---------------------------------------------------------------------------
// k2: out[b] = log(g_acc[b]); re-zero for next graph replay (proven pattern:
// statics start zeroed, every replay restores zeros after reading).
// ---------------------------------------------------------------------------
__global__ void k2_final(float* __restrict__ out) {
    int i = blockIdx.x * blockDim.x + threadIdx.x;
    if (i < B_SZ) {
        out[i] = logf(g_acc[i]);
        g_acc[i] = 0.0f;
    }
}

// ---------------------------------------------------------------------------
// Inputs (metadata order): d_in[0]=x int32 [1024,2], d_in[1]=W fp32 [2,256,256,256],
// d_in[2]=w_sum fp32 [256]. Output: fp32 [1024].
// ---------------------------------------------------------------------------
extern "C" void kernel_launch(void* const* d_in, const int* in_sizes, int n_in,
                              void* d_out, int out_size) {
    (void)in_sizes; (void)n_in; (void)out_size;
    const int2*  x     = (const int2*)d_in[0];
    const float* W     = (const float*)d_in[1];
    const float* w_sum = (const float*)d_in[2];
    float*       out   = (float*)d_out;

    static int smem_set = 0;
    if (!smem_set) {
        cudaFuncSetAttribute(k_gemm, cudaFuncAttributeMaxDynamicSharedMemorySize,
                             SMEM_TOTAL);
        smem_set = 1;
    }
    k_gemm<<<NCTA, THREADS, SMEM_TOTAL>>>(x, W, w_sum);
    k2_final<<<4, 256>>>(out);
}